// round 1
// baseline (speedup 1.0000x reference)
#include <cuda_runtime.h>

// ExpandEvecs: out[b,k,n,m] = sum_{j<=k} ev[b,n,j] * ev[b,m,j]
// ev: [B=4, C=1, N=1024, K=16] fp32 ; out: [B, K, N, N] fp32 (256 MB)
// Pure store-bound: 1 FMA per output element via running cumsum over k.

#define NDIM 1024
#define KDIM 16
#define TILE_N 16

__global__ __launch_bounds__(256, 2)
void expand_evecs_kernel(const float* __restrict__ ev, float* __restrict__ out) {
    const int b   = blockIdx.y;
    const int n0  = blockIdx.x * TILE_N;
    const int tid = threadIdx.x;
    const int m   = tid << 2;           // 4 consecutive m-columns per thread

    __shared__ float a_s[TILE_N][KDIM]; // 16 x 16 A-rows for this n-tile

    const float* evb = ev + (size_t)b * NDIM * KDIM;

    // Load A tile: 256 floats, one per thread. Row = tid>>4, col = tid&15,
    // which is exactly contiguous element evb[n0*16 + tid].
    a_s[tid >> 4][tid & 15] = evb[(size_t)n0 * KDIM + tid];

    // Load this thread's 4 B-rows (m..m+3), 16 floats each, as float4s.
    float bw[4][KDIM];
    const float4* evb4 = (const float4*)evb;
    #pragma unroll
    for (int i = 0; i < 4; ++i) {
        #pragma unroll
        for (int q = 0; q < 4; ++q) {
            ((float4*)bw[i])[q] = evb4[(size_t)(m + i) * (KDIM / 4) + q];
        }
    }
    __syncthreads();

    float* ob = out + (size_t)b * KDIM * NDIM * NDIM;

    for (int nn = 0; nn < TILE_N; ++nn) {
        float4 acc = make_float4(0.f, 0.f, 0.f, 0.f);
        float* orow = ob + (size_t)(n0 + nn) * NDIM + m;
        #pragma unroll
        for (int k = 0; k < KDIM; ++k) {
            const float ak = a_s[nn][k];
            acc.x = fmaf(ak, bw[0][k], acc.x);
            acc.y = fmaf(ak, bw[1][k], acc.y);
            acc.z = fmaf(ak, bw[2][k], acc.z);
            acc.w = fmaf(ak, bw[3][k], acc.w);
            *(float4*)(orow + (size_t)k * NDIM * NDIM) = acc;
        }
    }
}

extern "C" void kernel_launch(void* const* d_in, const int* in_sizes, int n_in,
                              void* d_out, int out_size) {
    const float* ev = (const float*)d_in[0];
    float* out = (float*)d_out;
    const int B = in_sizes[0] / (NDIM * KDIM);   // = 4
    dim3 grid(NDIM / TILE_N, B);
    expand_evecs_kernel<<<grid, 256>>>(ev, out);
}

// round 2
// speedup vs baseline: 1.0071x; 1.0071x over previous
#include <cuda_runtime.h>

// ExpandEvecs: out[b,k,n,m] = sum_{j<=k} ev[b,n,j] * ev[b,m,j]
// ev: [B=4, C=1, N=1024, K=16] fp32 ; out: [B, K, N, N] fp32 (256 MB)
// Pure store-bound. Persistent grid (296 = 2 CTA/SM on 148 SMs, also fits
// 152-SM GB300), contiguous work chunks for balance, evict-first stores.

#define NDIM 1024
#define KDIM 16
#define GRID_BLOCKS 296

__global__ __launch_bounds__(256, 2)
void expand_evecs_kernel(const float* __restrict__ ev,
                         float* __restrict__ out,
                         int n_items) {
    const int tid = threadIdx.x;
    const int m   = tid << 2;            // 4 consecutive m-columns per thread

    // Contiguous chunk of (b,n)-row work items for this block.
    const int per = n_items / GRID_BLOCKS;
    const int rem = n_items % GRID_BLOCKS;
    int start, count;
    if ((int)blockIdx.x < rem) {
        count = per + 1;
        start = blockIdx.x * count;
    } else {
        count = per;
        start = rem * (per + 1) + (blockIdx.x - rem) * per;
    }

    float bw[4][KDIM];                   // this thread's 4 B-rows (depends on b only)
    int cur_b = -1;

    for (int it = start; it < start + count; ++it) {
        const int b = it >> 10;          // NDIM = 1024
        const int n = it & (NDIM - 1);
        const float* evb = ev + (size_t)b * NDIM * KDIM;

        if (b != cur_b) {                // at most 2 distinct b per block
            const float4* evb4 = (const float4*)evb;
            #pragma unroll
            for (int i = 0; i < 4; ++i) {
                #pragma unroll
                for (int q = 0; q < 4; ++q)
                    ((float4*)bw[i])[q] = evb4[(size_t)(m + i) * (KDIM / 4) + q];
            }
            cur_b = b;
        }

        // a-row for this n: uniform across the block -> broadcast L1 hits.
        float a[KDIM];
        const float4* arow = (const float4*)(evb + (size_t)n * KDIM);
        #pragma unroll
        for (int q = 0; q < 4; ++q)
            ((float4*)a)[q] = __ldg(arow + q);

        float4 acc = make_float4(0.f, 0.f, 0.f, 0.f);
        float* orow = out + ((size_t)b * KDIM * NDIM + n) * NDIM + m;

        #pragma unroll
        for (int k = 0; k < KDIM; ++k) {
            acc.x = fmaf(a[k], bw[0][k], acc.x);
            acc.y = fmaf(a[k], bw[1][k], acc.y);
            acc.z = fmaf(a[k], bw[2][k], acc.z);
            acc.w = fmaf(a[k], bw[3][k], acc.w);
            __stcs((float4*)(orow + (size_t)k * NDIM * NDIM), acc);
        }
    }
}

extern "C" void kernel_launch(void* const* d_in, const int* in_sizes, int n_in,
                              void* d_out, int out_size) {
    const float* ev = (const float*)d_in[0];
    float* out = (float*)d_out;
    const int B = in_sizes[0] / (NDIM * KDIM);   // = 4
    const int n_items = B * NDIM;                // 4096 (b,n) rows
    expand_evecs_kernel<<<GRID_BLOCKS, 256>>>(ev, out, n_items);
}